// round 1
// baseline (speedup 1.0000x reference)
#include <cuda_runtime.h>

#define N_TOK 8192
#define EMB   1024
#define FFD   4096
#define SEQ   2048
#define NB    4
#define NH    16
#define HD    64

// ---------------- scratch (device globals: allocation-guard safe) ----------
__device__ float g_h [N_TOK * EMB];
__device__ float g_q [N_TOK * EMB];
__device__ float g_k [N_TOK * EMB];
__device__ float g_v [N_TOK * EMB];
__device__ float g_y [N_TOK * EMB];
__device__ float g_x2[N_TOK * EMB];
__device__ float g_ff[(size_t)N_TOK * FFD];

// ---------------- LayerNorm: one block per token row (1024 elems) ----------
__global__ __launch_bounds__(256)
void ln_kernel(const float* __restrict__ x, const float* __restrict__ g,
               const float* __restrict__ b, float* __restrict__ out)
{
    int row = blockIdx.x;
    const float* xr = x + (size_t)row * EMB;
    float4 v = ((const float4*)xr)[threadIdx.x];
    float s  = v.x + v.y + v.z + v.w;
    float ss = v.x*v.x + v.y*v.y + v.z*v.z + v.w*v.w;
    #pragma unroll
    for (int o = 16; o; o >>= 1) {
        s  += __shfl_xor_sync(0xffffffffu, s,  o);
        ss += __shfl_xor_sync(0xffffffffu, ss, o);
    }
    __shared__ float sh[8], sh2[8];
    int w = threadIdx.x >> 5, lane = threadIdx.x & 31;
    if (lane == 0) { sh[w] = s; sh2[w] = ss; }
    __syncthreads();
    if (w == 0) {
        s  = (lane < 8) ? sh[lane]  : 0.f;
        ss = (lane < 8) ? sh2[lane] : 0.f;
        #pragma unroll
        for (int o = 4; o; o >>= 1) {
            s  += __shfl_xor_sync(0xffffffffu, s,  o);
            ss += __shfl_xor_sync(0xffffffffu, ss, o);
        }
        if (lane == 0) { sh[0] = s; sh2[0] = ss; }
    }
    __syncthreads();
    float mu   = sh[0] * (1.f / EMB);
    float var  = sh2[0] * (1.f / EMB) - mu * mu;
    float rstd = rsqrtf(var + 1e-5f);
    float4 gg = ((const float4*)g)[threadIdx.x];
    float4 bb = ((const float4*)b)[threadIdx.x];
    float4 o4;
    o4.x = (v.x - mu) * rstd * gg.x + bb.x;
    o4.y = (v.y - mu) * rstd * gg.y + bb.y;
    o4.z = (v.z - mu) * rstd * gg.z + bb.z;
    o4.w = (v.w - mu) * rstd * gg.w + bb.w;
    ((float4*)(out + (size_t)row * EMB))[threadIdx.x] = o4;
}

// ---------------- SGEMM 128x128x8, 256 threads, 8x8 microtile --------------
// C[M,N] = A[M,K] @ B[K,N] + bias ; EPI: 0=bias, 1=bias+gelu, 2=bias+residual
template <int EPI>
__global__ __launch_bounds__(256)
void sgemm_kernel(const float* __restrict__ A, const float* __restrict__ B,
                  const float* __restrict__ bias, const float* __restrict__ R,
                  float* __restrict__ C, int M, int N, int K)
{
    __shared__ float As[8][128];
    __shared__ float Bs[8][128];
    int tid = threadIdx.x;
    int bx = blockIdx.x, by = blockIdx.y;
    const float* Ab = A + (size_t)by * 128 * K;
    const float* Bb = B + (size_t)bx * 128;
    int arow = tid >> 1, acol = (tid & 1) * 4;
    int brow = tid >> 5, bcol = (tid & 31) * 4;
    int tx = tid & 15, ty = tid >> 4;
    float acc[8][8];
    #pragma unroll
    for (int i = 0; i < 8; i++)
        #pragma unroll
        for (int j = 0; j < 8; j++) acc[i][j] = 0.f;

    for (int k0 = 0; k0 < K; k0 += 8) {
        float4 av = *(const float4*)(Ab + (size_t)arow * K + k0 + acol);
        float4 bv = *(const float4*)(Bb + (size_t)(k0 + brow) * N + bcol);
        As[acol + 0][arow] = av.x;
        As[acol + 1][arow] = av.y;
        As[acol + 2][arow] = av.z;
        As[acol + 3][arow] = av.w;
        *(float4*)&Bs[brow][bcol] = bv;
        __syncthreads();
        #pragma unroll
        for (int kk = 0; kk < 8; kk++) {
            float4 a0 = *(const float4*)&As[kk][ty * 8];
            float4 a1 = *(const float4*)&As[kk][ty * 8 + 4];
            float4 b0 = *(const float4*)&Bs[kk][tx * 8];
            float4 b1 = *(const float4*)&Bs[kk][tx * 8 + 4];
            float ra[8] = {a0.x, a0.y, a0.z, a0.w, a1.x, a1.y, a1.z, a1.w};
            float rb[8] = {b0.x, b0.y, b0.z, b0.w, b1.x, b1.y, b1.z, b1.w};
            #pragma unroll
            for (int i = 0; i < 8; i++)
                #pragma unroll
                for (int j = 0; j < 8; j++)
                    acc[i][j] += ra[i] * rb[j];
        }
        __syncthreads();
    }

    int row0 = by * 128 + ty * 8;
    int col0 = bx * 128 + tx * 8;
    #pragma unroll
    for (int i = 0; i < 8; i++) {
        int row = row0 + i;
        #pragma unroll
        for (int j = 0; j < 8; j++) {
            int col = col0 + j;
            float cv = acc[i][j] + bias[col];
            if (EPI == 1) cv = 0.5f * cv * (1.f + erff(cv * 0.70710678118654752f));
            if (EPI == 2) cv += R[(size_t)row * N + col];
            C[(size_t)row * N + col] = cv;
        }
    }
}

// ---------------- causal flash attention, fp32 -----------------------------
// q,k,v,y: token-major [B*S, EMB], head h occupies cols [h*64, h*64+64)
// grid (S/64, H, B), 256 threads; each thread owns a 4x4 microtile.
__global__ __launch_bounds__(256)
void attn_kernel(const float* __restrict__ q, const float* __restrict__ k,
                 const float* __restrict__ v, float* __restrict__ y)
{
    extern __shared__ float sm[];
    float* Qs = sm;               // [64 d][68]: Qs[d*68 + r]   (transposed, pad 4)
    float* Ks = sm + 64 * 68;     // scores: Ks[d*68 + c]; reused as Ps[c*68 + r]
    float* Vs = sm + 2 * 64 * 68; // Vs[kk*68 + d]

    int qt = blockIdx.x, h = blockIdx.y, b = blockIdx.z;
    int tid = threadIdx.x;
    int tx = tid & 15, ty = tid >> 4;
    int r0 = ty * 4, c0 = tx * 4;

    // load Q tile (scaled by 1/sqrt(64)), transposed into Qs[d][r]
    for (int i = tid; i < 1024; i += 256) {
        int row = i >> 4; int d4 = (i & 15) * 4;
        float4 qv = *(const float4*)(q + (size_t)(b * SEQ + qt * 64 + row) * EMB + h * HD + d4);
        Qs[(d4 + 0) * 68 + row] = qv.x * 0.125f;
        Qs[(d4 + 1) * 68 + row] = qv.y * 0.125f;
        Qs[(d4 + 2) * 68 + row] = qv.z * 0.125f;
        Qs[(d4 + 3) * 68 + row] = qv.w * 0.125f;
    }

    float m[4], l[4], o[4][4];
    #pragma unroll
    for (int ri = 0; ri < 4; ri++) {
        m[ri] = -1e30f; l[ri] = 0.f;
        #pragma unroll
        for (int ci = 0; ci < 4; ci++) o[ri][ci] = 0.f;
    }

    for (int kt = 0; kt <= qt; kt++) {
        __syncthreads();  // prior P/V consumption finished
        for (int i = tid; i < 1024; i += 256) {
            int row = i >> 4; int d4 = (i & 15) * 4;
            size_t tok = (size_t)(b * SEQ + kt * 64 + row) * EMB + h * HD + d4;
            float4 kv = *(const float4*)(k + tok);
            Ks[(d4 + 0) * 68 + row] = kv.x;
            Ks[(d4 + 1) * 68 + row] = kv.y;
            Ks[(d4 + 2) * 68 + row] = kv.z;
            Ks[(d4 + 3) * 68 + row] = kv.w;
            float4 vv = *(const float4*)(v + tok);
            *(float4*)&Vs[row * 68 + d4] = vv;
        }
        __syncthreads();

        // S = Q K^T (4x4 microtile per thread)
        float s[4][4];
        #pragma unroll
        for (int ri = 0; ri < 4; ri++)
            #pragma unroll
            for (int ci = 0; ci < 4; ci++) s[ri][ci] = 0.f;
        #pragma unroll 8
        for (int d = 0; d < 64; d++) {
            float4 qa = *(const float4*)&Qs[d * 68 + r0];
            float4 ka = *(const float4*)&Ks[d * 68 + c0];
            float ra[4] = {qa.x, qa.y, qa.z, qa.w};
            float rc[4] = {ka.x, ka.y, ka.z, ka.w};
            #pragma unroll
            for (int ri = 0; ri < 4; ri++)
                #pragma unroll
                for (int ci = 0; ci < 4; ci++)
                    s[ri][ci] += ra[ri] * rc[ci];
        }
        if (kt == qt) {
            #pragma unroll
            for (int ri = 0; ri < 4; ri++)
                #pragma unroll
                for (int ci = 0; ci < 4; ci++)
                    if (c0 + ci > r0 + ri) s[ri][ci] = -1e30f;
        }

        // row max across the 16 tx-lanes of each row group
        float rm[4];
        #pragma unroll
        for (int ri = 0; ri < 4; ri++)
            rm[ri] = fmaxf(fmaxf(s[ri][0], s[ri][1]), fmaxf(s[ri][2], s[ri][3]));
        #pragma unroll
        for (int off = 1; off < 16; off <<= 1)
            #pragma unroll
            for (int ri = 0; ri < 4; ri++)
                rm[ri] = fmaxf(rm[ri], __shfl_xor_sync(0xffffffffu, rm[ri], off));

        float corr[4], rs[4];
        #pragma unroll
        for (int ri = 0; ri < 4; ri++) {
            float mn = fmaxf(m[ri], rm[ri]);
            corr[ri] = __expf(m[ri] - mn);
            m[ri] = mn;
            float sum = 0.f;
            #pragma unroll
            for (int ci = 0; ci < 4; ci++) {
                float p = __expf(s[ri][ci] - mn);
                s[ri][ci] = p;
                sum += p;
            }
            rs[ri] = sum;
        }
        #pragma unroll
        for (int off = 1; off < 16; off <<= 1)
            #pragma unroll
            for (int ri = 0; ri < 4; ri++)
                rs[ri] += __shfl_xor_sync(0xffffffffu, rs[ri], off);
        #pragma unroll
        for (int ri = 0; ri < 4; ri++) {
            l[ri] = l[ri] * corr[ri] + rs[ri];
            #pragma unroll
            for (int ci = 0; ci < 4; ci++) o[ri][ci] *= corr[ri];
        }

        __syncthreads();  // everyone done reading Ks for scores
        #pragma unroll
        for (int ri = 0; ri < 4; ri++)
            #pragma unroll
            for (int ci = 0; ci < 4; ci++)
                Ks[(c0 + ci) * 68 + (r0 + ri)] = s[ri][ci];  // Ps[kcol][qrow]
        __syncthreads();

        // O += P @ V
        #pragma unroll 8
        for (int kk = 0; kk < 64; kk++) {
            float4 pa = *(const float4*)&Ks[kk * 68 + r0];
            float4 va = *(const float4*)&Vs[kk * 68 + c0];
            float rp[4] = {pa.x, pa.y, pa.z, pa.w};
            float rv[4] = {va.x, va.y, va.z, va.w};
            #pragma unroll
            for (int ri = 0; ri < 4; ri++)
                #pragma unroll
                for (int ci = 0; ci < 4; ci++)
                    o[ri][ci] += rp[ri] * rv[ci];
        }
    }

    #pragma unroll
    for (int ri = 0; ri < 4; ri++) {
        float inv = 1.f / l[ri];
        int row = qt * 64 + r0 + ri;
        float4 ov = {o[ri][0] * inv, o[ri][1] * inv, o[ri][2] * inv, o[ri][3] * inv};
        *(float4*)(y + (size_t)(b * SEQ + row) * EMB + h * HD + c0) = ov;
    }
}

// ---------------- launcher -------------------------------------------------
extern "C" void kernel_launch(void* const* d_in, const int* in_sizes, int n_in,
                              void* d_out, int out_size)
{
    const float* x     = (const float*)d_in[0];
    const float* Wq    = (const float*)d_in[1];
    const float* bq    = (const float*)d_in[2];
    const float* Wk    = (const float*)d_in[3];
    const float* bk    = (const float*)d_in[4];
    const float* Wv    = (const float*)d_in[5];
    const float* bv    = (const float*)d_in[6];
    const float* Wo    = (const float*)d_in[7];
    const float* bo    = (const float*)d_in[8];
    const float* g1    = (const float*)d_in[9];
    const float* beta1 = (const float*)d_in[10];
    const float* g2    = (const float*)d_in[11];
    const float* beta2 = (const float*)d_in[12];
    const float* W1    = (const float*)d_in[13];
    const float* b1f   = (const float*)d_in[14];
    const float* W2    = (const float*)d_in[15];
    const float* b2    = (const float*)d_in[16];
    float* out = (float*)d_out;

    float *h, *qb, *kb, *vb, *yb, *x2, *ff;
    cudaGetSymbolAddress((void**)&h,  g_h);
    cudaGetSymbolAddress((void**)&qb, g_q);
    cudaGetSymbolAddress((void**)&kb, g_k);
    cudaGetSymbolAddress((void**)&vb, g_v);
    cudaGetSymbolAddress((void**)&yb, g_y);
    cudaGetSymbolAddress((void**)&x2, g_x2);
    cudaGetSymbolAddress((void**)&ff, g_ff);

    cudaFuncSetAttribute(attn_kernel, cudaFuncAttributeMaxDynamicSharedMemorySize, 52224);

    dim3 grid1024(EMB / 128, N_TOK / 128);   // (8, 64)
    dim3 gridff(FFD / 128, N_TOK / 128);     // (32, 64)

    // h = LN1(x)
    ln_kernel<<<N_TOK, 256>>>(x, g1, beta1, h);
    // q,k,v = h @ W* + b*
    sgemm_kernel<0><<<grid1024, 256>>>(h, Wq, bq, nullptr, qb, N_TOK, EMB, EMB);
    sgemm_kernel<0><<<grid1024, 256>>>(h, Wk, bk, nullptr, kb, N_TOK, EMB, EMB);
    sgemm_kernel<0><<<grid1024, 256>>>(h, Wv, bv, nullptr, vb, N_TOK, EMB, EMB);
    // y = causal_softmax(q k^T / 8) v
    attn_kernel<<<dim3(SEQ / 64, NH, NB), 256, 52224>>>(qb, kb, vb, yb);
    // x2 = x + y @ Wo + bo
    sgemm_kernel<2><<<grid1024, 256>>>(yb, Wo, bo, x, x2, N_TOK, EMB, EMB);
    // h = LN2(x2)
    ln_kernel<<<N_TOK, 256>>>(x2, g2, beta2, h);
    // ff = gelu(h @ W1 + b1)
    sgemm_kernel<1><<<gridff, 256>>>(h, W1, b1f, nullptr, ff, N_TOK, FFD, EMB);
    // out = x2 + ff @ W2 + b2
    sgemm_kernel<2><<<grid1024, 256>>>(ff, W2, b2, x2, out, N_TOK, EMB, FFD);
}

// round 2
// speedup vs baseline: 1.8726x; 1.8726x over previous
#include <cuda_runtime.h>

#define N_TOK 8192
#define EMB   1024
#define FFD   4096
#define SEQ   2048
#define NB    4
#define NH    16
#define HD    64

// ---------------- scratch (device globals: allocation-guard safe) ----------
__device__ float g_h [N_TOK * EMB];
__device__ float g_q [N_TOK * EMB];
__device__ float g_k [N_TOK * EMB];
__device__ float g_v [N_TOK * EMB];
__device__ float g_y [N_TOK * EMB];
__device__ float g_x2[N_TOK * EMB];
__device__ float g_ff[(size_t)N_TOK * FFD];
// tf32-rounded weights
__device__ float g_wq[EMB * EMB];
__device__ float g_wk[EMB * EMB];
__device__ float g_wv[EMB * EMB];
__device__ float g_wo[EMB * EMB];
__device__ float g_w1[EMB * FFD];
__device__ float g_w2[FFD * EMB];

__device__ __forceinline__ float tf32r(float x) {
    unsigned u;
    asm("cvt.rna.tf32.f32 %0, %1;\n" : "=r"(u) : "f"(x));
    return __uint_as_float(u);
}

// ---------------- weight rounding (fp32 -> tf32-representable fp32) --------
__global__ __launch_bounds__(256)
void round_kernel(const float* __restrict__ in, float* __restrict__ out, int n4)
{
    int i = blockIdx.x * 256 + threadIdx.x;
    if (i < n4) {
        float4 v = ((const float4*)in)[i];
        v.x = tf32r(v.x); v.y = tf32r(v.y); v.z = tf32r(v.z); v.w = tf32r(v.w);
        ((float4*)out)[i] = v;
    }
}

// ---------------- LayerNorm (outputs tf32-rounded: feeds GEMM A) -----------
__global__ __launch_bounds__(256)
void ln_kernel(const float* __restrict__ x, const float* __restrict__ g,
               const float* __restrict__ b, float* __restrict__ out)
{
    int row = blockIdx.x;
    const float* xr = x + (size_t)row * EMB;
    float4 v = ((const float4*)xr)[threadIdx.x];
    float s  = v.x + v.y + v.z + v.w;
    float ss = v.x*v.x + v.y*v.y + v.z*v.z + v.w*v.w;
    #pragma unroll
    for (int o = 16; o; o >>= 1) {
        s  += __shfl_xor_sync(0xffffffffu, s,  o);
        ss += __shfl_xor_sync(0xffffffffu, ss, o);
    }
    __shared__ float sh[8], sh2[8];
    int w = threadIdx.x >> 5, lane = threadIdx.x & 31;
    if (lane == 0) { sh[w] = s; sh2[w] = ss; }
    __syncthreads();
    if (w == 0) {
        s  = (lane < 8) ? sh[lane]  : 0.f;
        ss = (lane < 8) ? sh2[lane] : 0.f;
        #pragma unroll
        for (int o = 4; o; o >>= 1) {
            s  += __shfl_xor_sync(0xffffffffu, s,  o);
            ss += __shfl_xor_sync(0xffffffffu, ss, o);
        }
        if (lane == 0) { sh[0] = s; sh2[0] = ss; }
    }
    __syncthreads();
    float mu   = sh[0] * (1.f / EMB);
    float var  = sh2[0] * (1.f / EMB) - mu * mu;
    float rstd = rsqrtf(var + 1e-5f);
    float4 gg = ((const float4*)g)[threadIdx.x];
    float4 bb = ((const float4*)b)[threadIdx.x];
    float4 o4;
    o4.x = tf32r((v.x - mu) * rstd * gg.x + bb.x);
    o4.y = tf32r((v.y - mu) * rstd * gg.y + bb.y);
    o4.z = tf32r((v.z - mu) * rstd * gg.z + bb.z);
    o4.w = tf32r((v.w - mu) * rstd * gg.w + bb.w);
    ((float4*)(out + (size_t)row * EMB))[threadIdx.x] = o4;
}

// ---------------- TF32 tensor-core GEMM ------------------------------------
// C[M,N] = A[M,K]@B[K,N] + bias ; EPI: 0=bias, 1=bias+gelu(+round), 2=bias+res
// 128x128x32 CTA tile, 256 thr (2x4 warps), warp 64x32, mma.m16n8k8 tf32.
#define TG_STAGES 3
#define AS_STRIDE 36
#define BS_STRIDE 136
#define AS_TILE (128 * AS_STRIDE)
#define BS_TILE (32 * BS_STRIDE)
#define TG_SMEM (TG_STAGES * (AS_TILE + BS_TILE) * 4)

__device__ __forceinline__ void mma_tf32(float* d, const unsigned* a, const unsigned* b)
{
    asm volatile(
        "mma.sync.aligned.m16n8k8.row.col.f32.tf32.tf32.f32 "
        "{%0,%1,%2,%3}, {%4,%5,%6,%7}, {%8,%9}, {%0,%1,%2,%3};\n"
        : "+f"(d[0]), "+f"(d[1]), "+f"(d[2]), "+f"(d[3])
        : "r"(a[0]), "r"(a[1]), "r"(a[2]), "r"(a[3]), "r"(b[0]), "r"(b[1]));
}

template <int EPI>
__global__ __launch_bounds__(256)
void tgemm_kernel(const float* __restrict__ A, const float* __restrict__ B,
                  const float* __restrict__ bias, const float* __restrict__ R,
                  float* __restrict__ C, int M, int N, int K)
{
    extern __shared__ float smbuf[];
    float* AsBase = smbuf;
    float* BsBase = smbuf + TG_STAGES * AS_TILE;

    int tid = threadIdx.x;
    int bx = blockIdx.x, by = blockIdx.y;

    // global->smem tile copy coords
    int ar = tid >> 1;              // A row 0..127
    int ak = (tid & 1) * 16;        // A k offset: 4 float4 at ak+4q
    int br = tid >> 3;              // B k-row 0..31
    int bn = (tid & 7) * 16;        // B n offset: 4 float4 at bn+4q
    const float* Ag = A + (size_t)(by * 128 + ar) * K + ak;
    const float* Bg = B + (size_t)br * N + bx * 128 + bn;

    auto issue_tile = [&](int kt, int s) {
        const float* ag = Ag + kt * 32;
        float* as = AsBase + s * AS_TILE + ar * AS_STRIDE + ak;
        #pragma unroll
        for (int q = 0; q < 4; q++) {
            unsigned d = (unsigned)__cvta_generic_to_shared(as + q * 4);
            asm volatile("cp.async.cg.shared.global [%0], [%1], 16;\n"
                         :: "r"(d), "l"(ag + q * 4));
        }
        const float* bg = Bg + (size_t)kt * 32 * N;
        float* bs = BsBase + s * BS_TILE + br * BS_STRIDE + bn;
        #pragma unroll
        for (int q = 0; q < 4; q++) {
            unsigned d = (unsigned)__cvta_generic_to_shared(bs + q * 4);
            asm volatile("cp.async.cg.shared.global [%0], [%1], 16;\n"
                         :: "r"(d), "l"(bg + q * 4));
        }
    };

    int ntiles = K >> 5;
    issue_tile(0, 0); asm volatile("cp.async.commit_group;\n");
    issue_tile(1, 1); asm volatile("cp.async.commit_group;\n");

    int wid = tid >> 5, lane = tid & 31;
    int wm = wid >> 2, wn = wid & 3;   // 2 x 4 warp grid
    int g = lane >> 2, t = lane & 3;

    float acc[4][4][4];
    #pragma unroll
    for (int mi = 0; mi < 4; mi++)
        #pragma unroll
        for (int ni = 0; ni < 4; ni++)
            #pragma unroll
            for (int r = 0; r < 4; r++) acc[mi][ni][r] = 0.f;

    for (int kt = 0; kt < ntiles; kt++) {
        asm volatile("cp.async.wait_group 1;\n");
        __syncthreads();
        if (kt + 2 < ntiles) issue_tile(kt + 2, (kt + 2) % 3);
        asm volatile("cp.async.commit_group;\n");

        int s = kt % 3;
        const unsigned* Asu = (const unsigned*)(AsBase + s * AS_TILE);
        const unsigned* Bsu = (const unsigned*)(BsBase + s * BS_TILE);
        #pragma unroll
        for (int kk = 0; kk < 32; kk += 8) {
            unsigned a[4][4], b[4][2];
            #pragma unroll
            for (int mi = 0; mi < 4; mi++) {
                int row = wm * 64 + mi * 16 + g;
                a[mi][0] = Asu[row * AS_STRIDE + kk + t];
                a[mi][1] = Asu[(row + 8) * AS_STRIDE + kk + t];
                a[mi][2] = Asu[row * AS_STRIDE + kk + t + 4];
                a[mi][3] = Asu[(row + 8) * AS_STRIDE + kk + t + 4];
            }
            #pragma unroll
            for (int ni = 0; ni < 4; ni++) {
                int col = wn * 32 + ni * 8 + g;
                b[ni][0] = Bsu[(kk + t) * BS_STRIDE + col];
                b[ni][1] = Bsu[(kk + t + 4) * BS_STRIDE + col];
            }
            #pragma unroll
            for (int mi = 0; mi < 4; mi++)
                #pragma unroll
                for (int ni = 0; ni < 4; ni++)
                    mma_tf32(acc[mi][ni], a[mi], b[ni]);
        }
    }

    // epilogue: c0,c1 at (g, 2t),(g, 2t+1); c2,c3 at (g+8, ...)
    #pragma unroll
    for (int mi = 0; mi < 4; mi++) {
        int row = by * 128 + wm * 64 + mi * 16 + g;
        #pragma unroll
        for (int ni = 0; ni < 4; ni++) {
            int col = bx * 128 + wn * 32 + ni * 8 + t * 2;
            float b0 = bias[col], b1 = bias[col + 1];
            float v0 = acc[mi][ni][0] + b0;
            float v1 = acc[mi][ni][1] + b1;
            float v2 = acc[mi][ni][2] + b0;
            float v3 = acc[mi][ni][3] + b1;
            if (EPI == 1) {
                v0 = tf32r(0.5f * v0 * (1.f + erff(v0 * 0.70710678118654752f)));
                v1 = tf32r(0.5f * v1 * (1.f + erff(v1 * 0.70710678118654752f)));
                v2 = tf32r(0.5f * v2 * (1.f + erff(v2 * 0.70710678118654752f)));
                v3 = tf32r(0.5f * v3 * (1.f + erff(v3 * 0.70710678118654752f)));
            }
            if (EPI == 2) {
                v0 += R[(size_t)row * N + col];
                v1 += R[(size_t)row * N + col + 1];
                v2 += R[(size_t)(row + 8) * N + col];
                v3 += R[(size_t)(row + 8) * N + col + 1];
            }
            *(float2*)(C + (size_t)row * N + col)       = make_float2(v0, v1);
            *(float2*)(C + (size_t)(row + 8) * N + col) = make_float2(v2, v3);
        }
    }
}

// ---------------- causal flash attention, fp32 (output tf32-rounded) -------
__global__ __launch_bounds__(256)
void attn_kernel(const float* __restrict__ q, const float* __restrict__ k,
                 const float* __restrict__ v, float* __restrict__ y)
{
    extern __shared__ float sm[];
    float* Qs = sm;               // Qs[d*68 + r] (transposed, pad 4)
    float* Ks = sm + 64 * 68;     // Ks[d*68 + c]; reused as Ps[c*68 + r]
    float* Vs = sm + 2 * 64 * 68; // Vs[kk*68 + d]

    int qt = blockIdx.x, h = blockIdx.y, b = blockIdx.z;
    int tid = threadIdx.x;
    int tx = tid & 15, ty = tid >> 4;
    int r0 = ty * 4, c0 = tx * 4;

    for (int i = tid; i < 1024; i += 256) {
        int row = i >> 4; int d4 = (i & 15) * 4;
        float4 qv = *(const float4*)(q + (size_t)(b * SEQ + qt * 64 + row) * EMB + h * HD + d4);
        Qs[(d4 + 0) * 68 + row] = qv.x * 0.125f;
        Qs[(d4 + 1) * 68 + row] = qv.y * 0.125f;
        Qs[(d4 + 2) * 68 + row] = qv.z * 0.125f;
        Qs[(d4 + 3) * 68 + row] = qv.w * 0.125f;
    }

    float m[4], l[4], o[4][4];
    #pragma unroll
    for (int ri = 0; ri < 4; ri++) {
        m[ri] = -1e30f; l[ri] = 0.f;
        #pragma unroll
        for (int ci = 0; ci < 4; ci++) o[ri][ci] = 0.f;
    }

    for (int kt = 0; kt <= qt; kt++) {
        __syncthreads();
        for (int i = tid; i < 1024; i += 256) {
            int row = i >> 4; int d4 = (i & 15) * 4;
            size_t tok = (size_t)(b * SEQ + kt * 64 + row) * EMB + h * HD + d4;
            float4 kv = *(const float4*)(k + tok);
            Ks[(d4 + 0) * 68 + row] = kv.x;
            Ks[(d4 + 1) * 68 + row] = kv.y;
            Ks[(d4 + 2) * 68 + row] = kv.z;
            Ks[(d4 + 3) * 68 + row] = kv.w;
            float4 vv = *(const float4*)(v + tok);
            *(float4*)&Vs[row * 68 + d4] = vv;
        }
        __syncthreads();

        float s[4][4];
        #pragma unroll
        for (int ri = 0; ri < 4; ri++)
            #pragma unroll
            for (int ci = 0; ci < 4; ci++) s[ri][ci] = 0.f;
        #pragma unroll 8
        for (int d = 0; d < 64; d++) {
            float4 qa = *(const float4*)&Qs[d * 68 + r0];
            float4 ka = *(const float4*)&Ks[d * 68 + c0];
            float ra[4] = {qa.x, qa.y, qa.z, qa.w};
            float rc[4] = {ka.x, ka.y, ka.z, ka.w};
            #pragma unroll
            for (int ri = 0; ri < 4; ri++)
                #pragma unroll
                for (int ci = 0; ci < 4; ci++)
                    s[ri][ci] += ra[ri] * rc[ci];
        }
        if (kt == qt) {
            #pragma unroll
            for (int ri = 0; ri < 4; ri++)
                #pragma unroll
                for (int ci = 0; ci < 4; ci++)
                    if (c0 + ci > r0 + ri) s[ri][ci] = -1e30f;
        }

        float rm[4];
        #pragma unroll
        for (int ri = 0; ri < 4; ri++)
            rm[ri] = fmaxf(fmaxf(s[ri][0], s[ri][1]), fmaxf(s[ri][2], s[ri][3]));
        #pragma unroll
        for (int off = 1; off < 16; off <<= 1)
            #pragma unroll
            for (int ri = 0; ri < 4; ri++)
                rm[ri] = fmaxf(rm[ri], __shfl_xor_sync(0xffffffffu, rm[ri], off));

        float corr[4], rs[4];
        #pragma unroll
        for (int ri = 0; ri < 4; ri++) {
            float mn = fmaxf(m[ri], rm[ri]);
            corr[ri] = __expf(m[ri] - mn);
            m[ri] = mn;
            float sum = 0.f;
            #pragma unroll
            for (int ci = 0; ci < 4; ci++) {
                float p = __expf(s[ri][ci] - mn);
                s[ri][ci] = p;
                sum += p;
            }
            rs[ri] = sum;
        }
        #pragma unroll
        for (int off = 1; off < 16; off <<= 1)
            #pragma unroll
            for (int ri = 0; ri < 4; ri++)
                rs[ri] += __shfl_xor_sync(0xffffffffu, rs[ri], off);
        #pragma unroll
        for (int ri = 0; ri < 4; ri++) {
            l[ri] = l[ri] * corr[ri] + rs[ri];
            #pragma unroll
            for (int ci = 0; ci < 4; ci++) o[ri][ci] *= corr[ri];
        }

        __syncthreads();
        #pragma unroll
        for (int ri = 0; ri < 4; ri++)
            #pragma unroll
            for (int ci = 0; ci < 4; ci++)
                Ks[(c0 + ci) * 68 + (r0 + ri)] = s[ri][ci];
        __syncthreads();

        #pragma unroll 8
        for (int kk = 0; kk < 64; kk++) {
            float4 pa = *(const float4*)&Ks[kk * 68 + r0];
            float4 va = *(const float4*)&Vs[kk * 68 + c0];
            float rp[4] = {pa.x, pa.y, pa.z, pa.w};
            float rv[4] = {va.x, va.y, va.z, va.w};
            #pragma unroll
            for (int ri = 0; ri < 4; ri++)
                #pragma unroll
                for (int ci = 0; ci < 4; ci++)
                    o[ri][ci] += rp[ri] * rv[ci];
        }
    }

    #pragma unroll
    for (int ri = 0; ri < 4; ri++) {
        float inv = 1.f / l[ri];
        int row = qt * 64 + r0 + ri;
        float4 ov = {tf32r(o[ri][0] * inv), tf32r(o[ri][1] * inv),
                     tf32r(o[ri][2] * inv), tf32r(o[ri][3] * inv)};
        *(float4*)(y + (size_t)(b * SEQ + row) * EMB + h * HD + c0) = ov;
    }
}

// ---------------- launcher -------------------------------------------------
extern "C" void kernel_launch(void* const* d_in, const int* in_sizes, int n_in,
                              void* d_out, int out_size)
{
    const float* x     = (const float*)d_in[0];
    const float* Wq    = (const float*)d_in[1];
    const float* bq    = (const float*)d_in[2];
    const float* Wk    = (const float*)d_in[3];
    const float* bk    = (const float*)d_in[4];
    const float* Wv    = (const float*)d_in[5];
    const float* bv    = (const float*)d_in[6];
    const float* Wo    = (const float*)d_in[7];
    const float* bo    = (const float*)d_in[8];
    const float* g1    = (const float*)d_in[9];
    const float* beta1 = (const float*)d_in[10];
    const float* g2    = (const float*)d_in[11];
    const float* beta2 = (const float*)d_in[12];
    const float* W1    = (const float*)d_in[13];
    const float* b1f   = (const float*)d_in[14];
    const float* W2    = (const float*)d_in[15];
    const float* b2    = (const float*)d_in[16];
    float* out = (float*)d_out;

    float *h, *qb, *kb, *vb, *yb, *x2, *ff;
    float *wq, *wk, *wv, *wo, *w1, *w2;
    cudaGetSymbolAddress((void**)&h,  g_h);
    cudaGetSymbolAddress((void**)&qb, g_q);
    cudaGetSymbolAddress((void**)&kb, g_k);
    cudaGetSymbolAddress((void**)&vb, g_v);
    cudaGetSymbolAddress((void**)&yb, g_y);
    cudaGetSymbolAddress((void**)&x2, g_x2);
    cudaGetSymbolAddress((void**)&ff, g_ff);
    cudaGetSymbolAddress((void**)&wq, g_wq);
    cudaGetSymbolAddress((void**)&wk, g_wk);
    cudaGetSymbolAddress((void**)&wv, g_wv);
    cudaGetSymbolAddress((void**)&wo, g_wo);
    cudaGetSymbolAddress((void**)&w1, g_w1);
    cudaGetSymbolAddress((void**)&w2, g_w2);

    cudaFuncSetAttribute(attn_kernel, cudaFuncAttributeMaxDynamicSharedMemorySize, 52224);
    cudaFuncSetAttribute(tgemm_kernel<0>, cudaFuncAttributeMaxDynamicSharedMemorySize, TG_SMEM);
    cudaFuncSetAttribute(tgemm_kernel<1>, cudaFuncAttributeMaxDynamicSharedMemorySize, TG_SMEM);
    cudaFuncSetAttribute(tgemm_kernel<2>, cudaFuncAttributeMaxDynamicSharedMemorySize, TG_SMEM);

    // round weights to tf32 grid (unbiased rna) once per launch
    round_kernel<<<1024, 256>>>(Wq, wq, 262144);
    round_kernel<<<1024, 256>>>(Wk, wk, 262144);
    round_kernel<<<1024, 256>>>(Wv, wv, 262144);
    round_kernel<<<1024, 256>>>(Wo, wo, 262144);
    round_kernel<<<4096, 256>>>(W1, w1, 1048576);
    round_kernel<<<4096, 256>>>(W2, w2, 1048576);

    dim3 grid1024(EMB / 128, N_TOK / 128);   // (8, 64)
    dim3 gridff(FFD / 128, N_TOK / 128);     // (32, 64)

    ln_kernel<<<N_TOK, 256>>>(x, g1, beta1, h);
    tgemm_kernel<0><<<grid1024, 256, TG_SMEM>>>(h, wq, bq, nullptr, qb, N_TOK, EMB, EMB);
    tgemm_kernel<0><<<grid1024, 256, TG_SMEM>>>(h, wk, bk, nullptr, kb, N_TOK, EMB, EMB);
    tgemm_kernel<0><<<grid1024, 256, TG_SMEM>>>(h, wv, bv, nullptr, vb, N_TOK, EMB, EMB);
    attn_kernel<<<dim3(SEQ / 64, NH, NB), 256, 52224>>>(qb, kb, vb, yb);
    tgemm_kernel<2><<<grid1024, 256, TG_SMEM>>>(yb, wo, bo, x, x2, N_TOK, EMB, EMB);
    ln_kernel<<<N_TOK, 256>>>(x2, g2, beta2, h);
    tgemm_kernel<1><<<gridff, 256, TG_SMEM>>>(h, w1, b1f, nullptr, ff, N_TOK, FFD, EMB);
    tgemm_kernel<2><<<grid1024, 256, TG_SMEM>>>(ff, w2, b2, x2, out, N_TOK, EMB, FFD);
}

// round 4
// speedup vs baseline: 2.5484x; 1.3609x over previous
#include <cuda_runtime.h>

#define N_TOK 8192
#define EMB   1024
#define FFD   4096
#define SEQ   2048
#define NB    4
#define NH    16
#define HD    64

// ---------------- scratch ----------------
__device__ float g_h  [N_TOK * EMB];
__device__ float g_qkv[(size_t)N_TOK * 3 * EMB];
__device__ float g_y  [N_TOK * EMB];
__device__ float g_x2 [N_TOK * EMB];
__device__ float g_ff [(size_t)N_TOK * FFD];
// transposed ([out][in]) tf32-rounded weights
__device__ float g_wqkv[3 * EMB * EMB];
__device__ float g_wot [EMB * EMB];
__device__ float g_w1t [(size_t)FFD * EMB];
__device__ float g_w2t [(size_t)EMB * FFD];
__device__ float g_bqkv[3 * EMB];

__device__ __forceinline__ float tf32r(float x) {
    unsigned u;
    asm("cvt.rna.tf32.f32 %0, %1;\n" : "=r"(u) : "f"(x));
    return __uint_as_float(u);
}

// fast exp on the FMA pipe (x <= ~0; exact enough for softmax)
__device__ __forceinline__ float fexp(float x) {
    float t = fmaxf(x * 1.4426950408889634f, -126.0f);
    float fm = t + 12582912.0f;                    // 1.5*2^23
    int   ib = __float_as_int(fm);
    float f  = t - (fm - 12582912.0f);             // frac in [-0.5, 0.5]
    float p = 1.33335581464284e-3f;
    p = fmaf(p, f, 9.61812910762848e-3f);
    p = fmaf(p, f, 5.55041086648216e-2f);
    p = fmaf(p, f, 2.40226506959101e-1f);
    p = fmaf(p, f, 6.93147180559945e-1f);
    p = fmaf(p, f, 1.0f);
    unsigned sc = ((unsigned)ib << 23) + 0x3f800000u;
    return p * __uint_as_float(sc);
}

__device__ __forceinline__ void ldsm4(unsigned& r0, unsigned& r1, unsigned& r2,
                                      unsigned& r3, unsigned addr) {
    asm volatile("ldmatrix.sync.aligned.m8n8.x4.shared.b16 {%0,%1,%2,%3}, [%4];\n"
                 : "=r"(r0), "=r"(r1), "=r"(r2), "=r"(r3) : "r"(addr));
}

__device__ __forceinline__ void mma_tf32(float* d, const unsigned* a, const unsigned* b) {
    asm volatile(
        "mma.sync.aligned.m16n8k8.row.col.f32.tf32.tf32.f32 "
        "{%0,%1,%2,%3}, {%4,%5,%6,%7}, {%8,%9}, {%0,%1,%2,%3};\n"
        : "+f"(d[0]), "+f"(d[1]), "+f"(d[2]), "+f"(d[3])
        : "r"(a[0]), "r"(a[1]), "r"(a[2]), "r"(a[3]), "r"(b[0]), "r"(b[1]));
}

// ---------------- weight transpose + tf32 round: in[K][N] -> out[N][K] -----
__global__ __launch_bounds__(256)
void trans_round(const float* __restrict__ in, float* __restrict__ out, int K, int N)
{
    __shared__ float t[32][33];
    int n0 = blockIdx.x * 32, k0 = blockIdx.y * 32;
    int x = threadIdx.x, y = threadIdx.y;   // 32 x 8
    #pragma unroll
    for (int i = 0; i < 32; i += 8)
        t[y + i][x] = in[(size_t)(k0 + y + i) * N + n0 + x];
    __syncthreads();
    #pragma unroll
    for (int i = 0; i < 32; i += 8)
        out[(size_t)(n0 + y + i) * K + k0 + x] = tf32r(t[x][y + i]);
}

__global__ void concat_bias(const float* a, const float* b, const float* c, float* o)
{
    int i = blockIdx.x * 256 + threadIdx.x;
    if (i < 3072) o[i] = (i < 1024) ? a[i] : (i < 2048 ? b[i - 1024] : c[i - 2048]);
}

// ---------------- LayerNorm (tf32-rounded output) --------------------------
__global__ __launch_bounds__(256)
void ln_kernel(const float* __restrict__ x, const float* __restrict__ g,
               const float* __restrict__ b, float* __restrict__ out)
{
    int row = blockIdx.x;
    float4 v = ((const float4*)(x + (size_t)row * EMB))[threadIdx.x];
    float s  = v.x + v.y + v.z + v.w;
    float ss = v.x*v.x + v.y*v.y + v.z*v.z + v.w*v.w;
    #pragma unroll
    for (int o = 16; o; o >>= 1) {
        s  += __shfl_xor_sync(0xffffffffu, s,  o);
        ss += __shfl_xor_sync(0xffffffffu, ss, o);
    }
    __shared__ float sh[8], sh2[8];
    int w = threadIdx.x >> 5, lane = threadIdx.x & 31;
    if (lane == 0) { sh[w] = s; sh2[w] = ss; }
    __syncthreads();
    if (w == 0) {
        s  = (lane < 8) ? sh[lane]  : 0.f;
        ss = (lane < 8) ? sh2[lane] : 0.f;
        #pragma unroll
        for (int o = 4; o; o >>= 1) {
            s  += __shfl_xor_sync(0xffffffffu, s,  o);
            ss += __shfl_xor_sync(0xffffffffu, ss, o);
        }
        if (lane == 0) { sh[0] = s; sh2[0] = ss; }
    }
    __syncthreads();
    float mu   = sh[0] * (1.f / EMB);
    float var  = sh2[0] * (1.f / EMB) - mu * mu;
    float rstd = rsqrtf(var + 1e-5f);
    float4 gg = ((const float4*)g)[threadIdx.x];
    float4 bb = ((const float4*)b)[threadIdx.x];
    float4 o4;
    o4.x = tf32r((v.x - mu) * rstd * gg.x + bb.x);
    o4.y = tf32r((v.y - mu) * rstd * gg.y + bb.y);
    o4.z = tf32r((v.z - mu) * rstd * gg.z + bb.z);
    o4.w = tf32r((v.w - mu) * rstd * gg.w + bb.w);
    ((float4*)(out + (size_t)row * EMB))[threadIdx.x] = o4;
}

// ---------------- TF32 GEMM, B transposed [N][K], ldmatrix fragments -------
// EPI: 0 = bias + tf32round, 1 = bias + gelu + round, 2 = bias + residual
#define TG_STAGES 3
#define TS 36
#define TILE_F (128 * TS)
#define TG_SMEM (TG_STAGES * 2 * TILE_F * 4)

template <int EPI>
__global__ __launch_bounds__(256)
void tgemm_kernel(const float* __restrict__ A, const float* __restrict__ Bt,
                  const float* __restrict__ bias, const float* __restrict__ R,
                  float* __restrict__ C, int M, int N, int K)
{
    extern __shared__ float smbuf[];
    float* AsBase = smbuf;
    float* BsBase = smbuf + TG_STAGES * TILE_F;

    int tid = threadIdx.x;
    int bx = blockIdx.x, by = blockIdx.y;

    int cr = tid >> 1;              // row (A) / n-row (B), 0..127
    int ck = (tid & 1) * 16;        // k offset
    const float* Ag = A  + (size_t)(by * 128 + cr) * K + ck;
    const float* Bg = Bt + (size_t)(bx * 128 + cr) * K + ck;

    auto issue_tile = [&](int kt, int s) {
        const float* ag = Ag + kt * 32;
        float* as = AsBase + s * TILE_F + cr * TS + ck;
        #pragma unroll
        for (int q = 0; q < 4; q++) {
            unsigned d = (unsigned)__cvta_generic_to_shared(as + q * 4);
            asm volatile("cp.async.cg.shared.global [%0], [%1], 16;\n"
                         :: "r"(d), "l"(ag + q * 4));
        }
        const float* bg = Bg + kt * 32;
        float* bs = BsBase + s * TILE_F + cr * TS + ck;
        #pragma unroll
        for (int q = 0; q < 4; q++) {
            unsigned d = (unsigned)__cvta_generic_to_shared(bs + q * 4);
            asm volatile("cp.async.cg.shared.global [%0], [%1], 16;\n"
                         :: "r"(d), "l"(bg + q * 4));
        }
    };

    int ntiles = K >> 5;
    issue_tile(0, 0); asm volatile("cp.async.commit_group;\n");
    issue_tile(1, 1); asm volatile("cp.async.commit_group;\n");

    int wid = tid >> 5, lane = tid & 31;
    int wm = wid >> 2, wn = wid & 3;   // 2 x 4 warps, warp tile 64x32
    int g = lane >> 2, t = lane & 3;
    int lrow = (lane & 7) + ((lane >> 3) & 1) * 8;
    int lk   = (lane >> 4) * 4;

    unsigned uA = (unsigned)__cvta_generic_to_shared(AsBase);
    unsigned uB = (unsigned)__cvta_generic_to_shared(BsBase);
    unsigned aoff = ((wm * 64 + lrow) * TS + lk) * 4;
    unsigned boff = ((wn * 32 + lrow) * TS + lk) * 4;

    float acc[4][4][4];
    #pragma unroll
    for (int mi = 0; mi < 4; mi++)
        #pragma unroll
        for (int ni = 0; ni < 4; ni++)
            #pragma unroll
            for (int r = 0; r < 4; r++) acc[mi][ni][r] = 0.f;

    for (int kt = 0; kt < ntiles; kt++) {
        asm volatile("cp.async.wait_group 1;\n");
        __syncthreads();
        if (kt + 2 < ntiles) issue_tile(kt + 2, (kt + 2) % 3);
        asm volatile("cp.async.commit_group;\n");

        int s = kt % 3;
        unsigned sA = uA + s * TILE_F * 4;
        unsigned sB = uB + s * TILE_F * 4;
        #pragma unroll
        for (int kk = 0; kk < 32; kk += 8) {
            unsigned a[4][4], bf[4][2];
            #pragma unroll
            for (int mi = 0; mi < 4; mi++)
                ldsm4(a[mi][0], a[mi][1], a[mi][2], a[mi][3],
                      sA + aoff + (mi * 16 * TS + kk) * 4);
            #pragma unroll
            for (int p = 0; p < 2; p++) {
                unsigned r0, r1, r2, r3;
                ldsm4(r0, r1, r2, r3, sB + boff + (p * 16 * TS + kk) * 4);
                bf[2*p][0] = r0; bf[2*p+1][0] = r1;
                bf[2*p][1] = r2; bf[2*p+1][1] = r3;
            }
            #pragma unroll
            for (int mi = 0; mi < 4; mi++)
                #pragma unroll
                for (int ni = 0; ni < 4; ni++)
                    mma_tf32(acc[mi][ni], a[mi], bf[ni]);
        }
    }

    #pragma unroll
    for (int mi = 0; mi < 4; mi++) {
        int row = by * 128 + wm * 64 + mi * 16 + g;
        #pragma unroll
        for (int ni = 0; ni < 4; ni++) {
            int col = bx * 128 + wn * 32 + ni * 8 + t * 2;
            float b0 = bias[col], b1 = bias[col + 1];
            float v0 = acc[mi][ni][0] + b0;
            float v1 = acc[mi][ni][1] + b1;
            float v2 = acc[mi][ni][2] + b0;
            float v3 = acc[mi][ni][3] + b1;
            if (EPI == 0) {
                v0 = tf32r(v0); v1 = tf32r(v1); v2 = tf32r(v2); v3 = tf32r(v3);
            }
            if (EPI == 1) {
                v0 = tf32r(0.5f * v0 * (1.f + erff(v0 * 0.70710678118654752f)));
                v1 = tf32r(0.5f * v1 * (1.f + erff(v1 * 0.70710678118654752f)));
                v2 = tf32r(0.5f * v2 * (1.f + erff(v2 * 0.70710678118654752f)));
                v3 = tf32r(0.5f * v3 * (1.f + erff(v3 * 0.70710678118654752f)));
            }
            if (EPI == 2) {
                v0 += R[(size_t)row * N + col];
                v1 += R[(size_t)row * N + col + 1];
                v2 += R[(size_t)(row + 8) * N + col];
                v3 += R[(size_t)(row + 8) * N + col + 1];
            }
            *(float2*)(C + (size_t)row * N + col)       = make_float2(v0, v1);
            *(float2*)(C + (size_t)(row + 8) * N + col) = make_float2(v2, v3);
        }
    }
}

// ---------------- tensor-core causal flash attention -----------------------
// qkv: [tok][3072] (q | k | v), y: [tok][1024]
#define AST 76
__global__ __launch_bounds__(128)
void attn_kernel(const float* __restrict__ qkv, float* __restrict__ y)
{
    extern __shared__ float sm[];
    float* Ks = sm;               // [key][d]   (B-operand layout for QK^T)
    float* Vt = sm + 64 * AST;    // [d][key]   (B-operand layout for PV)
    float* Ps = sm + 2 * 64 * AST;// Q staging, then P [qrow][key]

    int qt = (int)gridDim.x - 1 - (int)blockIdx.x;   // long CTAs first
    int h = blockIdx.y, b = blockIdx.z;
    int tid = threadIdx.x, wq = tid >> 5, lane = tid & 31;
    int g = lane >> 2, t = lane & 3;
    int lrow = (lane & 7) + ((lane >> 3) & 1) * 8;
    int lk   = (lane >> 4) * 4;

    const float* qkvb = qkv + (size_t)(b * SEQ) * 3072 + h * HD;

    // stage Q (scaled 1/8, exact) into Ps
    for (int i = tid; i < 1024; i += 128) {
        int row = i >> 4, d4 = (i & 15) * 4;
        float4 v = *(const float4*)(qkvb + (size_t)(qt * 64 + row) * 3072 + d4);
        float4 o4 = {v.x * 0.125f, v.y * 0.125f, v.z * 0.125f, v.w * 0.125f};
        *(float4*)&Ps[row * AST + d4] = o4;
    }
    __syncthreads();

    unsigned uK = (unsigned)__cvta_generic_to_shared(Ks);
    unsigned uV = (unsigned)__cvta_generic_to_shared(Vt);
    unsigned uP = (unsigned)__cvta_generic_to_shared(Ps);
    unsigned aoff = ((wq * 16 + lrow) * AST + lk) * 4;  // own-warp rows in Ps
    unsigned boff = (lrow * AST + lk) * 4;

    unsigned qa[8][4];
    #pragma unroll
    for (int kb = 0; kb < 8; kb++)
        ldsm4(qa[kb][0], qa[kb][1], qa[kb][2], qa[kb][3], uP + aoff + kb * 32);

    float oacc[8][4];
    #pragma unroll
    for (int nb = 0; nb < 8; nb++)
        #pragma unroll
        for (int r = 0; r < 4; r++) oacc[nb][r] = 0.f;
    float mr[2] = {-1e30f, -1e30f}, ls[2] = {0.f, 0.f};

    for (int kt = 0; kt <= qt; kt++) {
        __syncthreads();
        for (int i = tid; i < 1024; i += 128) {
            int row = i >> 4, d4 = (i & 15) * 4;
            const float* src = qkvb + (size_t)(kt * 64 + row) * 3072;
            float4 kv = *(const float4*)(src + 1024 + d4);
            *(float4*)&Ks[row * AST + d4] = kv;
            float4 vv = *(const float4*)(src + 2048 + d4);
            Vt[(d4 + 0) * AST + row] = vv.x;
            Vt[(d4 + 1) * AST + row] = vv.y;
            Vt[(d4 + 2) * AST + row] = vv.z;
            Vt[(d4 + 3) * AST + row] = vv.w;
        }
        __syncthreads();

        // S = Q K^T
        float sc[8][4];
        #pragma unroll
        for (int nb = 0; nb < 8; nb++)
            #pragma unroll
            for (int r = 0; r < 4; r++) sc[nb][r] = 0.f;
        #pragma unroll
        for (int kb = 0; kb < 8; kb++) {
            unsigned bk[8][2];
            #pragma unroll
            for (int p = 0; p < 4; p++) {
                unsigned r0, r1, r2, r3;
                ldsm4(r0, r1, r2, r3, uK + boff + (p * 16 * AST + kb * 8) * 4);
                bk[2*p][0] = r0; bk[2*p+1][0] = r1;
                bk[2*p][1] = r2; bk[2*p+1][1] = r3;
            }
            #pragma unroll
            for (int nb = 0; nb < 8; nb++)
                mma_tf32(sc[nb], qa[kb], bk[nb]);
        }

        if (kt == qt) {
            int row0 = wq * 16 + g;
            #pragma unroll
            for (int nb = 0; nb < 8; nb++) {
                int col = nb * 8 + 2 * t;
                if (col     > row0)     sc[nb][0] = -1e30f;
                if (col + 1 > row0)     sc[nb][1] = -1e30f;
                if (col     > row0 + 8) sc[nb][2] = -1e30f;
                if (col + 1 > row0 + 8) sc[nb][3] = -1e30f;
            }
        }

        // online softmax (rows g and g+8; reduce over 4 lanes sharing g)
        float rm0 = -1e30f, rm1 = -1e30f;
        #pragma unroll
        for (int nb = 0; nb < 8; nb++) {
            rm0 = fmaxf(rm0, fmaxf(sc[nb][0], sc[nb][1]));
            rm1 = fmaxf(rm1, fmaxf(sc[nb][2], sc[nb][3]));
        }
        rm0 = fmaxf(rm0, __shfl_xor_sync(0xffffffffu, rm0, 1));
        rm0 = fmaxf(rm0, __shfl_xor_sync(0xffffffffu, rm0, 2));
        rm1 = fmaxf(rm1, __shfl_xor_sync(0xffffffffu, rm1, 1));
        rm1 = fmaxf(rm1, __shfl_xor_sync(0xffffffffu, rm1, 2));
        float mn0 = fmaxf(mr[0], rm0), mn1 = fmaxf(mr[1], rm1);
        float co0 = fexp(mr[0] - mn0), co1 = fexp(mr[1] - mn1);
        mr[0] = mn0; mr[1] = mn1;

        float su0 = 0.f, su1 = 0.f;
        #pragma unroll
        for (int nb = 0; nb < 8; nb++) {
            float p0 = fexp(sc[nb][0] - mn0);
            float p1 = fexp(sc[nb][1] - mn0);
            float p2 = fexp(sc[nb][2] - mn1);
            float p3 = fexp(sc[nb][3] - mn1);
            su0 += p0 + p1; su1 += p2 + p3;
            int col = nb * 8 + 2 * t;
            *(float2*)&Ps[(wq * 16 + g)     * AST + col] = make_float2(tf32r(p0), tf32r(p1));
            *(float2*)&Ps[(wq * 16 + g + 8) * AST + col] = make_float2(tf32r(p2), tf32r(p3));
        }
        su0 += __shfl_xor_sync(0xffffffffu, su0, 1);
        su0 += __shfl_xor_sync(0xffffffffu, su0, 2);
        su1 += __shfl_xor_sync(0xffffffffu, su1, 1);
        su1 += __shfl_xor_sync(0xffffffffu, su1, 2);
        ls[0] = ls[0] * co0 + su0;
        ls[1] = ls[1] * co1 + su1;
        #pragma unroll
        for (int nb = 0; nb < 8; nb++) {
            oacc[nb][0] *= co0; oacc[nb][1] *= co0;
            oacc[nb][2] *= co1; oacc[nb][3] *= co1;
        }
        __syncwarp();

        // O += P V   (P from own-warp rows of Ps; V from Vt)
        #pragma unroll
        for (int kb = 0; kb < 8; kb++) {
            unsigned pa[4];
            ldsm4(pa[0], pa[1], pa[2], pa[3], uP + aoff + kb * 32);
            unsigned vb[8][2];
            #pragma unroll
            for (int p = 0; p < 4; p++) {
                unsigned r0, r1, r2, r3;
                ldsm4(r0, r1, r2, r3, uV + boff + (p * 16 * AST + kb * 8) * 4);
                vb[2*p][0] = r0; vb[2*p+1][0] = r1;
                vb[2*p][1] = r2; vb[2*p+1][1] = r3;
            }
            #pragma unroll
            for (int nb = 0; nb < 8; nb++)
                mma_tf32(oacc[nb], pa, vb[nb]);
        }
    }

    float inv0 = 1.f / ls[0], inv1 = 1.f / ls[1];
    int row0 = qt * 64 + wq * 16 + g;
    #pragma unroll
    for (int nb = 0; nb < 8; nb++) {
        int col = nb * 8 + 2 * t;
        *(float2*)(y + (size_t)(b * SEQ + row0) * EMB + h * HD + col) =
            make_float2(tf32r(oacc[nb][0] * inv0), tf32r(oacc[nb][1] * inv0));
        *(float2*)(y + (size_t)(b * SEQ + row0 + 8) * EMB + h * HD + col) =
            make_float2(tf32r(oacc[nb][2] * inv1), tf32r(oacc[nb][3] * inv1));
    }
}

// ---------------- launcher -------------------------------------------------
extern "C" void kernel_launch(void* const* d_in, const int* in_sizes, int n_in,
                              void* d_out, int out_size)
{
    const float* x     = (const float*)d_in[0];
    const float* Wq    = (const float*)d_in[1];
    const float* bq    = (const float*)d_in[2];
    const float* Wk    = (const float*)d_in[3];
    const float* bk    = (const float*)d_in[4];
    const float* Wv    = (const float*)d_in[5];
    const float* bv    = (const float*)d_in[6];
    const float* Wo    = (const float*)d_in[7];
    const float* bo    = (const float*)d_in[8];
    const float* g1    = (const float*)d_in[9];
    const float* beta1 = (const float*)d_in[10];
    const float* g2    = (const float*)d_in[11];
    const float* beta2 = (const float*)d_in[12];
    const float* W1    = (const float*)d_in[13];
    const float* b1f   = (const float*)d_in[14];
    const float* W2    = (const float*)d_in[15];
    const float* b2    = (const float*)d_in[16];
    float* out = (float*)d_out;

    float *h, *qkv, *yb, *x2, *ff, *wqkv, *wot, *w1t, *w2t, *bqkv;
    cudaGetSymbolAddress((void**)&h,    g_h);
    cudaGetSymbolAddress((void**)&qkv,  g_qkv);
    cudaGetSymbolAddress((void**)&yb,   g_y);
    cudaGetSymbolAddress((void**)&x2,   g_x2);
    cudaGetSymbolAddress((void**)&ff,   g_ff);
    cudaGetSymbolAddress((void**)&wqkv, g_wqkv);
    cudaGetSymbolAddress((void**)&wot,  g_wot);
    cudaGetSymbolAddress((void**)&w1t,  g_w1t);
    cudaGetSymbolAddress((void**)&w2t,  g_w2t);
    cudaGetSymbolAddress((void**)&bqkv, g_bqkv);

    cudaFuncSetAttribute(attn_kernel, cudaFuncAttributeMaxDynamicSharedMemorySize, 3 * 64 * AST * 4);
    cudaFuncSetAttribute(tgemm_kernel<0>, cudaFuncAttributeMaxDynamicSharedMemorySize, TG_SMEM);
    cudaFuncSetAttribute(tgemm_kernel<1>, cudaFuncAttributeMaxDynamicSharedMemorySize, TG_SMEM);
    cudaFuncSetAttribute(tgemm_kernel<2>, cudaFuncAttributeMaxDynamicSharedMemorySize, TG_SMEM);

    dim3 tb(32, 8);
    // transpose + round weights: out rows = output features
    trans_round<<<dim3(EMB/32,  EMB/32), tb>>>(Wq, wqkv,                 EMB, EMB);
    trans_round<<<dim3(EMB/32,  EMB/32), tb>>>(Wk, wqkv + EMB*EMB,       EMB, EMB);
    trans_round<<<dim3(EMB/32,  EMB/32), tb>>>(Wv, wqkv + 2*EMB*EMB,     EMB, EMB);
    trans_round<<<dim3(EMB/32,  EMB/32), tb>>>(Wo, wot,                  EMB, EMB);
    trans_round<<<dim3(FFD/32,  EMB/32), tb>>>(W1, w1t,                  EMB, FFD);
    trans_round<<<dim3(EMB/32,  FFD/32), tb>>>(W2, w2t,                  FFD, EMB);
    concat_bias<<<12, 256>>>(bq, bk, bv, bqkv);

    dim3 gqkv(3 * EMB / 128, N_TOK / 128);   // (24, 64)
    dim3 g1024(EMB / 128, N_TOK / 128);      // (8, 64)
    dim3 gff(FFD / 128, N_TOK / 128);        // (32, 64)

    ln_kernel<<<N_TOK, 256>>>(x, g1, beta1, h);
    tgemm_kernel<0><<<gqkv, 256, TG_SMEM>>>(h, wqkv, bqkv, nullptr, qkv, N_TOK, 3 * EMB, EMB);
    attn_kernel<<<dim3(SEQ / 64, NH, NB), 128, 3 * 64 * AST * 4>>>(qkv, yb);
    tgemm_kernel<2><<<g1024, 256, TG_SMEM>>>(yb, wot, bo, x, x2, N_TOK, EMB, EMB);
    ln_kernel<<<N_TOK, 256>>>(x2, g2, beta2, h);
    tgemm_kernel<1><<<gff, 256, TG_SMEM>>>(h, w1t, b1f, nullptr, ff, N_TOK, FFD, EMB);
    tgemm_kernel<2><<<g1024, 256, TG_SMEM>>>(ff, w2t, b2, x2, out, N_TOK, EMB, FFD);
}

// round 6
// speedup vs baseline: 5.3644x; 2.1050x over previous
#include <cuda_runtime.h>
#include <cuda_fp16.h>

#define N_TOK 8192
#define EMB   1024
#define FFD   4096
#define SEQ   2048
#define NB    4
#define NH    16
#define HD    64

// ---------------- scratch ----------------
__device__ __half g_h  [N_TOK * EMB];
__device__ __half g_qkv[(size_t)N_TOK * 3 * EMB];
__device__ __half g_y  [N_TOK * EMB];
__device__ float  g_x2 [N_TOK * EMB];
__device__ __half g_ff [(size_t)N_TOK * FFD];
// transposed ([out][in]) fp16 weights
__device__ __half g_wqkv[3 * EMB * EMB];
__device__ __half g_wot [EMB * EMB];
__device__ __half g_w1t [(size_t)FFD * EMB];
__device__ __half g_w2t [(size_t)EMB * FFD];
__device__ float  g_bqkv[3 * EMB];

// fast exp on the FMA pipe
__device__ __forceinline__ float fexp(float x) {
    float t = fmaxf(x * 1.4426950408889634f, -126.0f);
    float fm = t + 12582912.0f;
    int   ib = __float_as_int(fm);
    float f  = t - (fm - 12582912.0f);
    float p = 1.33335581464284e-3f;
    p = fmaf(p, f, 9.61812910762848e-3f);
    p = fmaf(p, f, 5.55041086648216e-2f);
    p = fmaf(p, f, 2.40226506959101e-1f);
    p = fmaf(p, f, 6.93147180559945e-1f);
    p = fmaf(p, f, 1.0f);
    unsigned sc = ((unsigned)ib << 23) + 0x3f800000u;
    return p * __uint_as_float(sc);
}

__device__ __forceinline__ void ldsm4(unsigned& r0, unsigned& r1, unsigned& r2,
                                      unsigned& r3, unsigned addr) {
    asm volatile("ldmatrix.sync.aligned.m8n8.x4.shared.b16 {%0,%1,%2,%3}, [%4];\n"
                 : "=r"(r0), "=r"(r1), "=r"(r2), "=r"(r3) : "r"(addr));
}

// fp16 mma, fp32 accumulate
__device__ __forceinline__ void mma_f16(float* d, const unsigned* a, const unsigned* b) {
    asm volatile(
        "mma.sync.aligned.m16n8k16.row.col.f32.f16.f16.f32 "
        "{%0,%1,%2,%3}, {%4,%5,%6,%7}, {%8,%9}, {%0,%1,%2,%3};\n"
        : "+f"(d[0]), "+f"(d[1]), "+f"(d[2]), "+f"(d[3])
        : "r"(a[0]), "r"(a[1]), "r"(a[2]), "r"(a[3]), "r"(b[0]), "r"(b[1]));
}

__device__ __forceinline__ unsigned smem_u32(const void* p) {
    unsigned a;
    asm("{ .reg .u64 t; cvta.to.shared.u64 t, %1; cvt.u32.u64 %0, t; }"
        : "=r"(a) : "l"(p));
    return a;
}

// ---------------- weight prep: transpose + fp32 -> fp16 --------------------
__global__ __launch_bounds__(256)
void prep_all(const float* __restrict__ Wq, const float* __restrict__ Wk,
              const float* __restrict__ Wv, const float* __restrict__ Wo,
              const float* __restrict__ W1, const float* __restrict__ W2,
              __half* __restrict__ wqkv, __half* __restrict__ wot,
              __half* __restrict__ w1t, __half* __restrict__ w2t)
{
    int bid = blockIdx.x;
    const float* src; __half* dst; int K, N, base;
    if      (bid <  1024) { src = Wq; dst = wqkv;                   K = 1024; N = 1024; base = bid; }
    else if (bid <  2048) { src = Wk; dst = wqkv + 1024 * 1024;     K = 1024; N = 1024; base = bid - 1024; }
    else if (bid <  3072) { src = Wv; dst = wqkv + 2 * 1024 * 1024; K = 1024; N = 1024; base = bid - 2048; }
    else if (bid <  4096) { src = Wo; dst = wot;                    K = 1024; N = 1024; base = bid - 3072; }
    else if (bid <  8192) { src = W1; dst = w1t;                    K = 1024; N = 4096; base = bid - 4096; }
    else                  { src = W2; dst = w2t;                    K = 4096; N = 1024; base = bid - 8192; }
    int nb = N >> 5;
    int n0 = (base % nb) * 32, k0 = (base / nb) * 32;
    __shared__ float t[32][33];
    int x = threadIdx.x, y = threadIdx.y;
    #pragma unroll
    for (int i = 0; i < 32; i += 8)
        t[y + i][x] = src[(size_t)(k0 + y + i) * N + n0 + x];
    __syncthreads();
    #pragma unroll
    for (int i = 0; i < 32; i += 8)
        dst[(size_t)(n0 + y + i) * K + k0 + x] = __float2half_rn(t[x][y + i]);
}

__global__ void concat_bias(const float* a, const float* b, const float* c, float* o)
{
    int i = blockIdx.x * 256 + threadIdx.x;
    if (i < 3072) o[i] = (i < 1024) ? a[i] : (i < 2048 ? b[i - 1024] : c[i - 2048]);
}

// ---------------- LayerNorm (fp16 output) ----------------------------------
__global__ __launch_bounds__(256)
void ln_kernel(const float* __restrict__ x, const float* __restrict__ g,
               const float* __restrict__ b, __half* __restrict__ out)
{
    int row = blockIdx.x;
    float4 v = ((const float4*)(x + (size_t)row * EMB))[threadIdx.x];
    float s  = v.x + v.y + v.z + v.w;
    float ss = v.x*v.x + v.y*v.y + v.z*v.z + v.w*v.w;
    #pragma unroll
    for (int o = 16; o; o >>= 1) {
        s  += __shfl_xor_sync(0xffffffffu, s,  o);
        ss += __shfl_xor_sync(0xffffffffu, ss, o);
    }
    __shared__ float sh[8], sh2[8];
    int w = threadIdx.x >> 5, lane = threadIdx.x & 31;
    if (lane == 0) { sh[w] = s; sh2[w] = ss; }
    __syncthreads();
    if (w == 0) {
        s  = (lane < 8) ? sh[lane]  : 0.f;
        ss = (lane < 8) ? sh2[lane] : 0.f;
        #pragma unroll
        for (int o = 4; o; o >>= 1) {
            s  += __shfl_xor_sync(0xffffffffu, s,  o);
            ss += __shfl_xor_sync(0xffffffffu, ss, o);
        }
        if (lane == 0) { sh[0] = s; sh2[0] = ss; }
    }
    __syncthreads();
    float mu   = sh[0] * (1.f / EMB);
    float var  = sh2[0] * (1.f / EMB) - mu * mu;
    float rstd = rsqrtf(var + 1e-5f);
    float4 gg = ((const float4*)g)[threadIdx.x];
    float4 bb = ((const float4*)b)[threadIdx.x];
    __half2 h0 = __floats2half2_rn((v.x - mu) * rstd * gg.x + bb.x,
                                   (v.y - mu) * rstd * gg.y + bb.y);
    __half2 h1 = __floats2half2_rn((v.z - mu) * rstd * gg.z + bb.z,
                                   (v.w - mu) * rstd * gg.w + bb.w);
    uint2 u = make_uint2(*(unsigned*)&h0, *(unsigned*)&h1);
    ((uint2*)(out + (size_t)row * EMB))[threadIdx.x] = u;
}

// ==================== fp16 mma.sync GEMM ====================
// C[8192,N] = A[8192,K]@Bt[N,K]^T + bias. 128x128 CTA tile, k-slab 32 (fp16).
// 256 thr = 2x4 warps, warp 64x32. 3-stage cp.async.
// EPI: 0 = bias (half out), 1 = bias+gelu (half out), 2 = bias+residual (float out)
#define STG_B 20480                    // (128+128) rows * 80 B
#define TGEMM_SMEM (3 * STG_B)

template <int EPI, typename OutT>
__global__ __launch_bounds__(256)
void tgemm(const __half* __restrict__ A, const __half* __restrict__ Bt,
           const float* __restrict__ bias, const float* __restrict__ R,
           OutT* __restrict__ C, int N, int K)
{
    extern __shared__ char smem[];
    unsigned sbase = smem_u32(smem);
    int tid = threadIdx.x;
    int bx = blockIdx.x, by = blockIdx.y;

    size_t rowb = (size_t)K * 2;       // bytes per global row
    const char* Ag = (const char*)(A  + (size_t)(by * 128) * K);
    const char* Bg = (const char*)(Bt + (size_t)(bx * 128) * K);
    int crow = tid >> 2, cq = (tid & 3) * 16;   // 16B chunk coords (+128 rows on 2nd iter)

    auto issue_tile = [&](int kt, int s) {
        unsigned stA = sbase + s * STG_B;
        unsigned stB = stA + 10240;
        size_t kofs = (size_t)kt * 64;
        #pragma unroll
        for (int i = 0; i < 2; i++) {
            int row = crow + i * 64;
            unsigned d = stA + row * 80 + cq;
            asm volatile("cp.async.ca.shared.global [%0], [%1], 16;"
                         :: "r"(d), "l"(Ag + (size_t)row * rowb + kofs + cq));
            unsigned d2 = stB + row * 80 + cq;
            asm volatile("cp.async.ca.shared.global [%0], [%1], 16;"
                         :: "r"(d2), "l"(Bg + (size_t)row * rowb + kofs + cq));
        }
    };

    int T = K >> 5;
    issue_tile(0, 0); asm volatile("cp.async.commit_group;");
    issue_tile(1, 1); asm volatile("cp.async.commit_group;");

    int wid = tid >> 5, lane = tid & 31;
    int wm = wid >> 2, wn = wid & 3;
    int g = lane >> 2, t = lane & 3;
    int lrow = (lane & 7) + ((lane >> 3) & 1) * 8;
    int lk   = (lane >> 4) * 16;       // bytes

    unsigned aoffb = (wm * 64 + lrow) * 80 + lk;
    unsigned boffb = (wn * 32 + lrow) * 80 + lk;

    float acc[4][4][4];
    #pragma unroll
    for (int mi = 0; mi < 4; mi++)
        #pragma unroll
        for (int ni = 0; ni < 4; ni++)
            #pragma unroll
            for (int r = 0; r < 4; r++) acc[mi][ni][r] = 0.f;

    for (int kt = 0; kt < T; kt++) {
        asm volatile("cp.async.wait_group 1;");
        __syncthreads();
        if (kt + 2 < T) issue_tile(kt + 2, (kt + 2) % 3);
        asm volatile("cp.async.commit_group;");

        int s = kt % 3;
        unsigned sA = sbase + s * STG_B;
        unsigned sB = sA + 10240;
        #pragma unroll
        for (int kk = 0; kk < 2; kk++) {
            unsigned a[4][4], bf[4][2];
            #pragma unroll
            for (int mi = 0; mi < 4; mi++)
                ldsm4(a[mi][0], a[mi][1], a[mi][2], a[mi][3],
                      sA + aoffb + mi * 16 * 80 + kk * 32);
            #pragma unroll
            for (int p = 0; p < 2; p++) {
                unsigned r0, r1, r2, r3;
                ldsm4(r0, r1, r2, r3, sB + boffb + p * 16 * 80 + kk * 32);
                bf[2*p][0] = r0; bf[2*p][1] = r2;
                bf[2*p+1][0] = r1; bf[2*p+1][1] = r3;
            }
            #pragma unroll
            for (int mi = 0; mi < 4; mi++)
                #pragma unroll
                for (int ni = 0; ni < 4; ni++)
                    mma_f16(acc[mi][ni], a[mi], bf[ni]);
        }
    }

    #pragma unroll
    for (int mi = 0; mi < 4; mi++) {
        int row = by * 128 + wm * 64 + mi * 16 + g;
        #pragma unroll
        for (int ni = 0; ni < 4; ni++) {
            int col = bx * 128 + wn * 32 + ni * 8 + t * 2;
            float b0 = bias[col], b1 = bias[col + 1];
            float v0 = acc[mi][ni][0] + b0;
            float v1 = acc[mi][ni][1] + b1;
            float v2 = acc[mi][ni][2] + b0;
            float v3 = acc[mi][ni][3] + b1;
            if (EPI == 1) {
                v0 = 0.5f * v0 * (1.f + erff(v0 * 0.70710678118654752f));
                v1 = 0.5f * v1 * (1.f + erff(v1 * 0.70710678118654752f));
                v2 = 0.5f * v2 * (1.f + erff(v2 * 0.70710678118654752f));
                v3 = 0.5f * v3 * (1.f + erff(v3 * 0.70710678118654752f));
            }
            if (EPI == 2) {
                v0 += R[(size_t)row * N + col];
                v1 += R[(size_t)row * N + col + 1];
                v2 += R[(size_t)(row + 8) * N + col];
                v3 += R[(size_t)(row + 8) * N + col + 1];
            }
            if constexpr (sizeof(OutT) == 2) {
                __half2 h01 = __floats2half2_rn(v0, v1);
                __half2 h23 = __floats2half2_rn(v2, v3);
                *(__half2*)((__half*)C + (size_t)row * N + col)       = h01;
                *(__half2*)((__half*)C + (size_t)(row + 8) * N + col) = h23;
            } else {
                *(float2*)((float*)C + (size_t)row * N + col)       = make_float2(v0, v1);
                *(float2*)((float*)C + (size_t)(row + 8) * N + col) = make_float2(v2, v3);
            }
        }
    }
}

// ---------------- fp16 tensor-core causal flash attention ------------------
// qkv: half [tok][3072] (q|k|v), y: half [tok][1024]
#define AST2 72
__global__ __launch_bounds__(128)
void attn_kernel(const __half* __restrict__ qkv, __half* __restrict__ y)
{
    extern __shared__ __half smh[];
    __half* Ks = smh;                 // [key][d]  k-contig
    __half* Vt = smh + 64 * AST2;     // [d][key]  key-contig
    __half* Ps = smh + 2 * 64 * AST2; // Q staging, then P [qrow][key]

    int qt = (int)gridDim.x - 1 - (int)blockIdx.x;
    int h = blockIdx.y, b = blockIdx.z;
    int tid = threadIdx.x, wq = tid >> 5, lane = tid & 31;
    int g = lane >> 2, t = lane & 3;
    int lrow = (lane & 7) + ((lane >> 3) & 1) * 8;
    int lk   = (lane >> 4) * 16;      // bytes

    const __half* qkvb = qkv + (size_t)(b * SEQ) * 3072 + h * HD;

    // stage Q (scaled by 1/8, exact exponent shift) into Ps
    __half2 sc8 = __float2half2_rn(0.125f);
    for (int i = tid; i < 1024; i += 128) {
        int row = i >> 4, d4 = (i & 15) * 4;
        const __half2* src = (const __half2*)(qkvb + (size_t)(qt * 64 + row) * 3072 + d4);
        *(__half2*)&Ps[row * AST2 + d4]     = __hmul2(src[0], sc8);
        *(__half2*)&Ps[row * AST2 + d4 + 2] = __hmul2(src[1], sc8);
    }
    __syncthreads();

    unsigned uK = smem_u32(Ks), uV = smem_u32(Vt), uP = smem_u32(Ps);
    unsigned aoffb = (wq * 16 + lrow) * (AST2 * 2) + lk;
    unsigned boffb = lrow * (AST2 * 2) + lk;

    unsigned qa[4][4];
    #pragma unroll
    for (int kb = 0; kb < 4; kb++)
        ldsm4(qa[kb][0], qa[kb][1], qa[kb][2], qa[kb][3], uP + aoffb + kb * 32);

    float oacc[8][4];
    #pragma unroll
    for (int nb = 0; nb < 8; nb++)
        #pragma unroll
        for (int r = 0; r < 4; r++) oacc[nb][r] = 0.f;
    float mr[2] = {-1e30f, -1e30f}, ls[2] = {0.f, 0.f};

    for (int kt = 0; kt <= qt; kt++) {
        __syncthreads();
        for (int i = tid; i < 1024; i += 128) {
            int row = i >> 4, d4 = (i & 15) * 4;
            const __half* src = qkvb + (size_t)(kt * 64 + row) * 3072;
            *(__half2*)&Ks[row * AST2 + d4]     = *(const __half2*)(src + 1024 + d4);
            *(__half2*)&Ks[row * AST2 + d4 + 2] = *(const __half2*)(src + 1024 + d4 + 2);
            __half2 v0 = *(const __half2*)(src + 2048 + d4);
            __half2 v1 = *(const __half2*)(src + 2048 + d4 + 2);
            Vt[(d4 + 0) * AST2 + row] = __low2half(v0);
            Vt[(d4 + 1) * AST2 + row] = __high2half(v0);
            Vt[(d4 + 2) * AST2 + row] = __low2half(v1);
            Vt[(d4 + 3) * AST2 + row] = __high2half(v1);
        }
        __syncthreads();

        // S = Q K^T
        float sc[8][4];
        #pragma unroll
        for (int nb = 0; nb < 8; nb++)
            #pragma unroll
            for (int r = 0; r < 4; r++) sc[nb][r] = 0.f;
        #pragma unroll
        for (int kb = 0; kb < 4; kb++) {
            unsigned bk[8][2];
            #pragma unroll
            for (int p = 0; p < 4; p++) {
                unsigned r0, r1, r2, r3;
                ldsm4(r0, r1, r2, r3, uK + boffb + p * 16 * (AST2 * 2) + kb * 32);
                bk[2*p][0] = r0; bk[2*p][1] = r2;
                bk[2*p+1][0] = r1; bk[2*p+1][1] = r3;
            }
            #pragma unroll
            for (int nb = 0; nb < 8; nb++)
                mma_f16(sc[nb], qa[kb], bk[nb]);
        }

        if (kt == qt) {
            int row0 = wq * 16 + g;
            #pragma unroll
            for (int nb = 0; nb < 8; nb++) {
                int col = nb * 8 + 2 * t;
                if (col     > row0)     sc[nb][0] = -1e30f;
                if (col + 1 > row0)     sc[nb][1] = -1e30f;
                if (col     > row0 + 8) sc[nb][2] = -1e30f;
                if (col + 1 > row0 + 8) sc[nb][3] = -1e30f;
            }
        }

        float rm0 = -1e30f, rm1 = -1e30f;
        #pragma unroll
        for (int nb = 0; nb < 8; nb++) {
            rm0 = fmaxf(rm0, fmaxf(sc[nb][0], sc[nb][1]));
            rm1 = fmaxf(rm1, fmaxf(sc[nb][2], sc[nb][3]));
        }
        rm0 = fmaxf(rm0, __shfl_xor_sync(0xffffffffu, rm0, 1));
        rm0 = fmaxf(rm0, __shfl_xor_sync(0xffffffffu, rm0, 2));
        rm1 = fmaxf(rm1, __shfl_xor_sync(0xffffffffu, rm1, 1));
        rm1 = fmaxf(rm1, __shfl_xor_sync(0xffffffffu, rm1, 2));
        float mn0 = fmaxf(mr[0], rm0), mn1 = fmaxf(mr[1], rm1);
        float co0 = fexp(mr[0] - mn0), co1 = fexp(mr[1] - mn1);
        mr[0] = mn0; mr[1] = mn1;

        float su0 = 0.f, su1 = 0.f;
        #pragma unroll
        for (int nb = 0; nb < 8; nb++) {
            float p0 = fexp(sc[nb][0] - mn0);
            float p1 = fexp(sc[nb][1] - mn0);
            float p2 = fexp(sc[nb][2] - mn1);
            float p3 = fexp(sc[nb][3] - mn1);
            su0 += p0 + p1; su1 += p2 + p3;
            int col = nb * 8 + 2 * t;
            *(__half2*)&Ps[(wq * 16 + g)     * AST2 + col] = __floats2half2_rn(p0, p1);
            *(__half2*)&Ps[(wq * 16 + g + 8) * AST2 + col] = __floats2half2_rn(p2, p3);
        }
        su0 += __shfl_xor_sync(0xffffffffu, su0, 1);
        su0 += __shfl_xor_sync(0xffffffffu, su0, 2);
        su1 += __shfl_xor_sync(0xffffffffu, su1, 1);
        su1 += __shfl_xor_sync(0xffffffffu, su1, 2);
        ls[0] = ls[0] * co0 + su0;
        ls[1] = ls[1] * co1 + su1;
        #pragma unroll
        for (int nb = 0; nb < 8; nb++) {
            oacc[nb][0] *= co0; oacc[nb][1] *= co0;
            oacc[nb][2] *= co1; oacc[nb][3] *= co1;
        }
        __syncwarp();

        // O += P V
        #pragma unroll
        for (int kb = 0; kb < 4; kb++) {
            unsigned pa[4];
            ldsm4(pa[0], pa[1], pa[2], pa[3], uP + aoffb + kb * 32);
            unsigned vb[8][2];
            #pragma unroll
            for (int p = 0; p < 4; p++) {
                unsigned r0, r1, r2, r3;
                ldsm4(r0, r1, r2, r3, uV + boffb + p * 16 * (AST2 * 2) + kb * 32);
                vb[2*p][0] = r0; vb[2*p][1] = r2;
                vb[2*p+1][0] = r1; vb[2*p+1][1] = r3;
            }
            #pragma unroll
            for (int nb = 0; nb < 8; nb++)
                mma_f16(oacc[nb], pa, vb[nb]);
        }
    }

    float inv0 = 1.f / ls[0], inv1 = 1.f / ls[1];
    int row0 = qt * 64 + wq * 16 + g;
    #pragma unroll
    for (int nb = 0; nb < 8; nb++) {
        int col = nb * 8 + 2 * t;
        *(__half2*)(y + (size_t)(b * SEQ + row0) * EMB + h * HD + col) =
            __floats2half2_rn(oacc[nb][0] * inv0, oacc[nb][1] * inv0);
        *(__half2*)(y + (size_t)(b * SEQ + row0 + 8) * EMB + h * HD + col) =
            __floats2half2_rn(oacc[nb][2] * inv1, oacc[nb][3] * inv1);
    }
}

// ---------------- launcher -------------------------------------------------
extern "C" void kernel_launch(void* const* d_in, const int* in_sizes, int n_in,
                              void* d_out, int out_size)
{
    const float* x     = (const float*)d_in[0];
    const float* Wq    = (const float*)d_in[1];
    const float* bq    = (const float*)d_in[2];
    const float* Wk    = (const float*)d_in[3];
    const float* bk    = (const float*)d_in[4];
    const float* Wv    = (const float*)d_in[5];
    const float* bv    = (const float*)d_in[6];
    const float* Wo    = (const float*)d_in[7];
    const float* bo    = (const float*)d_in[8];
    const float* g1    = (const float*)d_in[9];
    const float* beta1 = (const float*)d_in[10];
    const float* g2    = (const float*)d_in[11];
    const float* beta2 = (const float*)d_in[12];
    const float* W1    = (const float*)d_in[13];
    const float* b1f   = (const float*)d_in[14];
    const float* W2    = (const float*)d_in[15];
    const float* b2    = (const float*)d_in[16];
    float* out = (float*)d_out;

    __half *h, *qkv, *yb, *ff, *wqkv, *wot, *w1t, *w2t;
    float *x2, *bqkv;
    cudaGetSymbolAddress((void**)&h,    g_h);
    cudaGetSymbolAddress((void**)&qkv,  g_qkv);
    cudaGetSymbolAddress((void**)&yb,   g_y);
    cudaGetSymbolAddress((void**)&x2,   g_x2);
    cudaGetSymbolAddress((void**)&ff,   g_ff);
    cudaGetSymbolAddress((void**)&wqkv, g_wqkv);
    cudaGetSymbolAddress((void**)&wot,  g_wot);
    cudaGetSymbolAddress((void**)&w1t,  g_w1t);
    cudaGetSymbolAddress((void**)&w2t,  g_w2t);
    cudaGetSymbolAddress((void**)&bqkv, g_bqkv);

    cudaFuncSetAttribute(tgemm<0, __half>, cudaFuncAttributeMaxDynamicSharedMemorySize, TGEMM_SMEM);
    cudaFuncSetAttribute(tgemm<1, __half>, cudaFuncAttributeMaxDynamicSharedMemorySize, TGEMM_SMEM);
    cudaFuncSetAttribute(tgemm<2, float>,  cudaFuncAttributeMaxDynamicSharedMemorySize, TGEMM_SMEM);

    // 0,1: prep
    prep_all<<<12288, dim3(32, 8)>>>(Wq, Wk, Wv, Wo, W1, W2, wqkv, wot, w1t, w2t);
    concat_bias<<<12, 256>>>(bq, bk, bv, bqkv);

    // 2..8: pipeline
    ln_kernel<<<N_TOK, 256>>>(x, g1, beta1, h);
    tgemm<0, __half><<<dim3(24, 64), 256, TGEMM_SMEM>>>(h, wqkv, bqkv, nullptr, qkv, 3 * EMB, EMB);
    attn_kernel<<<dim3(SEQ / 64, NH, NB), 128, 3 * 64 * AST2 * 2>>>(qkv, yb);
    tgemm<2, float><<<dim3(8, 64), 256, TGEMM_SMEM>>>(yb, wot, bo, x, x2, EMB, EMB);
    ln_kernel<<<N_TOK, 256>>>(x2, g2, beta2, h);
    tgemm<1, __half><<<dim3(32, 64), 256, TGEMM_SMEM>>>(h, w1t, b1f, nullptr, ff, FFD, EMB);
    tgemm<2, float><<<dim3(8, 64), 256, TGEMM_SMEM>>>(ff, w2t, b2, x2, out, EMB, FFD);
}